// round 16
// baseline (speedup 1.0000x reference)
#include <cuda_runtime.h>
#include <cuda_fp16.h>
#include <stdint.h>
#include <math.h>

namespace {
constexpr int NB  = 8;
constexpr int NG  = 2048;
constexpr int FIN = 32;
constexpr int TT  = 10;
constexpr int H   = 64;
constexpr int NN  = NB * NG;          // 16384
constexpr int NE  = 262144;
constexpr int KFX = 26 * FIN;         // 832
constexpr int KFH = 26 * H;           // 1664
constexpr int NSK = 4;                // h-side split-K factor
constexpr int KH4 = KFH / NSK;        // 416 per split
constexpr int OX  = 192;
constexpr int OH  = 128;
constexpr long long LOUT = (long long)NN * H * TT;
}

// ---------------- scratch (device globals; allocation-free contract) --------
__device__ int    g_is64;
__device__ int    g_bad64;
__device__ int    g_cnt[NN];
__device__ int    g_cnt2[NN];
__device__ int    g_rowptr[NN + 1];
__device__ float  g_invdeg[NN];
__device__ int    g_eid[NE];
__device__ int    g_esrc[NE];
__device__ int    g_ew00[NE];
__device__ __align__(16) float4 g_eb[NE];
__device__ __align__(16) float  g_xT[(size_t)TT * NN * FIN];
__device__ __align__(16) __half g_Ux[(size_t)TT * NN * KFX];   // fp16 U (x side)
__device__ __align__(16) __half g_Uh[(size_t)NN * KFH];        // fp16 U (h side)
__device__ __align__(16) __half g_WxT[OX * KFX];               // [n][k] fp16
__device__ __align__(16) __half g_WhT[OH * KFH];               // [n][k] fp16
__device__ __align__(16) float  g_CX[(size_t)TT * NN * OX];
__device__ __align__(16) float  g_CHp[NSK * (size_t)NN * OH];  // split-K partials
__device__ __align__(16) float  g_h [(size_t)NN * H];
__device__ __align__(16) float  g_hs[(size_t)TT * NN * H];

// ---------------- host-side streams/events (created at load, no dev allocs) --
static cudaStream_t s_sx = nullptr;
static cudaEvent_t  s_fork = nullptr;
static cudaEvent_t  s_evx[TT];
static struct SInit {
    SInit() {
        cudaStreamCreate(&s_sx);
        cudaEventCreateWithFlags(&s_fork, cudaEventDisableTiming);
        for (int t = 0; t < TT; ++t)
            cudaEventCreateWithFlags(&s_evx[t], cudaEventDisableTiming);
    }
} s_init;

// ---------------- helpers -----------------------------------------------------
__device__ __forceinline__ void cpasync16(void* smem, const void* g) {
    uint32_t s = (uint32_t)__cvta_generic_to_shared(smem);
    asm volatile("cp.async.ca.shared.global [%0], [%1], 16;\n" :: "r"(s), "l"(g));
}

// edge_index dtype helpers (int64 vs int32, decided at runtime by k_detect)
__device__ __forceinline__ int edge_src(const void* ei, int e) {
    return g_is64 ? (int)((const long long*)ei)[e] : ((const int*)ei)[e];
}
__device__ __forceinline__ int edge_dst(const void* ei, int e) {
    return g_is64 ? (int)((const long long*)ei)[NE + e] : ((const int*)ei)[NE + e];
}

// ---------------- init / dtype detection ------------------------------------
__global__ void k_init() {
    int idx = blockIdx.x * blockDim.x + threadIdx.x;
    if (idx < NN * H) g_h[idx] = 0.f;
    if (idx < NN) { g_cnt[idx] = 0; g_cnt2[idx] = 0; }
    if (idx == 0) { g_bad64 = 0; g_is64 = 1; }
}

__global__ void k_detect(const long long* __restrict__ ei64) {
    int i = blockIdx.x * blockDim.x + threadIdx.x;
    int bad = 0;
    for (; i < NE; i += gridDim.x * blockDim.x) {
        long long v = ei64[i];
        if (v < 0 || v >= NN) bad = 1;
    }
    if (__syncthreads_or(bad) && threadIdx.x == 0) atomicExch(&g_bad64, 1);
}
__global__ void k_detect_fin() { g_is64 = g_bad64 ? 0 : 1; }

// ---------------- graph preprocessing ----------------------------------------
__global__ void k_hist(const void* __restrict__ ei) {
    int e = blockIdx.x * blockDim.x + threadIdx.x;
    if (e < NE) atomicAdd(&g_cnt[edge_dst(ei, e)], 1);
}

__global__ void k_scan() {
    __shared__ int s[1024];
    __shared__ int carry;
    int tid = threadIdx.x;
    if (tid == 0) { carry = 0; g_rowptr[0] = 0; }
    __syncthreads();
    for (int c = 0; c < NN / 1024; ++c) {
        int i = c * 1024 + tid;
        int v = g_cnt[i];
        s[tid] = v;
        __syncthreads();
        for (int off = 1; off < 1024; off <<= 1) {
            int t = (tid >= off) ? s[tid - off] : 0;
            __syncthreads();
            s[tid] += t;
            __syncthreads();
        }
        g_rowptr[i + 1] = carry + s[tid];
        g_invdeg[i] = 1.0f / (float)max(v, 1);
        __syncthreads();
        if (tid == 0) carry += s[1023];
        __syncthreads();
    }
}

__global__ void k_scatterpos(const void* __restrict__ ei) {
    int e = blockIdx.x * blockDim.x + threadIdx.x;
    if (e < NE) {
        int dst = edge_dst(ei, e);
        g_eid[g_rowptr[dst] + atomicAdd(&g_cnt2[dst], 1)] = e;
    }
}

__global__ void k_sort() {   // deterministic per-bucket edge order
    int d = blockIdx.x * blockDim.x + threadIdx.x;
    if (d >= NN) return;
    int s0 = g_rowptr[d], e0 = g_rowptr[d + 1];
    for (int i = s0 + 1; i < e0; ++i) {
        int key = g_eid[i];
        int j = i - 1;
        while (j >= s0 && g_eid[j] > key) { g_eid[j + 1] = g_eid[j]; --j; }
        g_eid[j + 1] = key;
    }
}

__global__ void k_edgedata(const void* __restrict__ ei,
                           const float* __restrict__ attr) {
    int p = blockIdx.x * blockDim.x + threadIdx.x;
    if (p >= NE) return;
    int e = g_eid[p];
    float f0 = attr[2 * e]     * 4.0f;
    float f1 = attr[2 * e + 1] * 4.0f;
    int k0 = (int)floorf(f0); k0 = k0 < 0 ? 0 : (k0 > 3 ? 3 : k0);
    int k1 = (int)floorf(f1); k1 = k1 < 0 ? 0 : (k1 > 3 ? 3 : k1);
    float t0 = f0 - (float)k0, t1 = f1 - (float)k1;
    g_esrc[p] = edge_src(ei, e);
    g_ew00[p] = k0 + 5 * k1;
    g_eb[p] = make_float4((1.f - t0) * (1.f - t1), t0 * (1.f - t1),
                          (1.f - t0) * t1,          t0 * t1);
}

__global__ void k_xT(const float* __restrict__ x) {   // [n][f][t] -> [t][n][f]
    int idx = blockIdx.x * blockDim.x + threadIdx.x;
    if (idx >= NN * FIN) return;
    const float* src = x + (size_t)idx * TT;
#pragma unroll
    for (int t = 0; t < TT; ++t)
        g_xT[(size_t)t * NN * FIN + idx] = src[t];
}

// ---------------- weight concat: transposed [n][k], fp16 ---------------------
__global__ void k_build_wxT(const float* __restrict__ Wr, const float* __restrict__ Wz,
                            const float* __restrict__ Wn, const float* __restrict__ Rr,
                            const float* __restrict__ Rz, const float* __restrict__ Rn) {
    int idx = blockIdx.x * blockDim.x + threadIdx.x;
    if (idx >= OX * KFX) return;
    int n = idx / KFX, r = idx % KFX;
    int grp = n / 64, cc = n % 64;
    const float* W = (grp == 0) ? Wr : (grp == 1) ? Wz : Wn;
    const float* R = (grp == 0) ? Rr : (grp == 1) ? Rz : Rn;
    float val;
    if (r < 25 * FIN) { int k = r / FIN, f = r % FIN; val = W[((size_t)k * FIN + f) * H + cc]; }
    else              { int f = r - 25 * FIN;         val = R[(size_t)f * H + cc]; }
    g_WxT[idx] = __float2half_rn(val);
}

__global__ void k_build_whT(const float* __restrict__ Wr, const float* __restrict__ Wz,
                            const float* __restrict__ Rr, const float* __restrict__ Rz) {
    int idx = blockIdx.x * blockDim.x + threadIdx.x;
    if (idx >= OH * KFH) return;
    int n = idx / KFH, r = idx % KFH;
    int grp = n >> 6, cc = n & 63;
    const float* W = (grp == 0) ? Wr : Wz;
    const float* R = (grp == 0) ? Rr : Rz;
    float val;
    if (r < 25 * H) { int k = r / H, f = r % H; val = W[((size_t)k * H + f) * H + cc]; }
    else            { int f = r - 25 * H;       val = R[(size_t)f * H + cc]; }
    g_WhT[idx] = __float2half_rn(val);
}

// ---------------- scatter-aggregate (emits fp16 U) ---------------------------
template<int FV, bool XM>
__global__ void k_scatter(int tparam) {
    constexpr int NPC = 256 / FV;
    __shared__ float acc[NPC * 25 * FV];
    int t     = XM ? blockIdx.y : tparam;
    int tid   = threadIdx.x;
    int local = tid / FV;
    int f     = tid % FV;
    int node  = blockIdx.x * NPC + local;
    float* a = acc + local * (25 * FV) + f;
#pragma unroll
    for (int k = 0; k < 25; ++k) a[k * FV] = 0.f;

    const float* __restrict__ v = XM ? (g_xT + (size_t)t * NN * FIN) : g_h;
    int s = g_rowptr[node], e = g_rowptr[node + 1];
    for (int p = s; p < e; ++p) {
        float  vf = v[(size_t)g_esrc[p] * FV + f];
        float4 b  = g_eb[p];
        float* q  = a + g_ew00[p] * FV;
        q[0]      += b.x * vf;
        q[FV]     += b.y * vf;
        q[5 * FV] += b.z * vf;
        q[6 * FV] += b.w * vf;
    }
    float id = g_invdeg[node];
    __half* __restrict__ U = XM ? (g_Ux + (size_t)t * NN * KFX) : g_Uh;
    size_t ro = (size_t)node * (26 * FV);
#pragma unroll
    for (int k = 0; k < 25; ++k) U[ro + k * FV + f] = __float2half_rn(a[k * FV] * id);
    U[ro + 25 * FV + f] = __float2half_rn(v[(size_t)node * FV + f]);
}

// ---------------- x-side FP16 GEMM: BM=64, BN=192 (full), BK=32, occ 3 -------
// CX[t][N][192] = Ux[t][N][832] x WxT[192][832]^T   (t passed as param)
__global__ __launch_bounds__(256, 3)
void k_gemm_x(int t) {
    constexpr int BM = 64, BK = 32;
    constexpr int ASD = BK + 8;    // 40 halves
    constexpr int BKD = BK + 8;    // 40 halves, B stored [n][k]
    __shared__ __half As[2][BM * ASD];
    __shared__ __half Bs[2][OX * BKD];

    const __half* __restrict__ A = g_Ux + (size_t)t * NN * KFX;
    float* __restrict__ C        = g_CX + (size_t)t * NN * OX;

    int tid  = threadIdx.x;
    int lane = tid & 31, w = tid >> 5;
    int wm = w >> 2, wn = w & 3;
    int g  = lane >> 2, tq = lane & 3;
    int m_cta = blockIdx.x * BM;

    int a_row = tid >> 2, a_c8 = tid & 3;

    float acc[2][6][4];
#pragma unroll
    for (int i = 0; i < 2; ++i)
#pragma unroll
        for (int j = 0; j < 6; ++j)
#pragma unroll
            for (int q = 0; q < 4; ++q) acc[i][j][q] = 0.f;

    const __half* Ag0 = A + (size_t)m_cta * KFX;

#define XLOAD(kt, buf)                                                         \
    {                                                                          \
        cpasync16(&As[buf][a_row * ASD + a_c8 * 8],                            \
                  Ag0 + (size_t)a_row * KFX + (kt) * BK + a_c8 * 8);           \
        _Pragma("unroll")                                                      \
        for (int i = 0; i < 3; ++i) {                                          \
            int f4 = tid + i * 256;                                            \
            int nn = f4 >> 2, c8 = f4 & 3;                                     \
            cpasync16(&Bs[buf][nn * BKD + c8 * 8],                             \
                      g_WxT + (size_t)nn * KFX + (kt) * BK + c8 * 8);          \
        }                                                                      \
        asm volatile("cp.async.commit_group;");                                \
    }

    constexpr int NT = KFX / BK;   // 26
    XLOAD(0, 0);
    for (int kt = 0; kt < NT; ++kt) {
        asm volatile("cp.async.wait_group 0;");
        __syncthreads();
        if (kt + 1 < NT) XLOAD(kt + 1, (kt + 1) & 1);

        const __half* as = As[kt & 1];
        const __half* bs = Bs[kt & 1];
#pragma unroll
        for (int k16 = 0; k16 < 2; ++k16) {
            uint32_t af[2][4], bf[6][2];
#pragma unroll
            for (int mf = 0; mf < 2; ++mf) {
                int mrow = wm * 32 + mf * 16 + g;
                int kb = k16 * 16 + 2 * tq;
                af[mf][0] = *(const uint32_t*)&as[mrow * ASD + kb];
                af[mf][1] = *(const uint32_t*)&as[(mrow + 8) * ASD + kb];
                af[mf][2] = *(const uint32_t*)&as[mrow * ASD + kb + 8];
                af[mf][3] = *(const uint32_t*)&as[(mrow + 8) * ASD + kb + 8];
            }
#pragma unroll
            for (int nf = 0; nf < 6; ++nf) {
                int ncol = wn * 48 + nf * 8 + g;
                int kb = k16 * 16 + 2 * tq;
                bf[nf][0] = *(const uint32_t*)&bs[ncol * BKD + kb];
                bf[nf][1] = *(const uint32_t*)&bs[ncol * BKD + kb + 8];
            }
#pragma unroll
            for (int mf = 0; mf < 2; ++mf)
#pragma unroll
                for (int nf = 0; nf < 6; ++nf)
                    asm volatile(
                        "mma.sync.aligned.m16n8k16.row.col.f32.f16.f16.f32 "
                        "{%0,%1,%2,%3}, {%4,%5,%6,%7}, {%8,%9}, {%0,%1,%2,%3};"
                        : "+f"(acc[mf][nf][0]), "+f"(acc[mf][nf][1]),
                          "+f"(acc[mf][nf][2]), "+f"(acc[mf][nf][3])
                        : "r"(af[mf][0]), "r"(af[mf][1]),
                          "r"(af[mf][2]), "r"(af[mf][3]),
                          "r"(bf[nf][0]), "r"(bf[nf][1]));
        }
    }
#undef XLOAD

#pragma unroll
    for (int mf = 0; mf < 2; ++mf)
#pragma unroll
        for (int nf = 0; nf < 6; ++nf) {
            int row = m_cta + wm * 32 + mf * 16 + g;
            int col = wn * 48 + nf * 8 + 2 * tq;
            *(float2*)&C[(size_t)row * OX + col] =
                make_float2(acc[mf][nf][0], acc[mf][nf][1]);
            *(float2*)&C[(size_t)(row + 8) * OX + col] =
                make_float2(acc[mf][nf][2], acc[mf][nf][3]);
        }
}

// ---------------- h-side FP16 GEMM, split-K=4, occ 4 -------------------------
// CHp[ks][N][128] = Uh[N][ks*416 .. +416] x WhT[128][same]^T
__global__ __launch_bounds__(256, 4)
void k_gemm_h_sk(int t) {
    constexpr int BM = 64, BK = 32;
    constexpr int ASD = BK + 8;    // 40 halves
    constexpr int BKD = BK + 8;    // 40 halves
    __shared__ __half As[2][BM * ASD];
    __shared__ __half Bs[2][OH * BKD];

    int ks = blockIdx.y;
    int kbase = ks * KH4;

    int tid  = threadIdx.x;
    int lane = tid & 31, w = tid >> 5;
    int wm = w >> 2, wn = w & 3;
    int g  = lane >> 2, tq = lane & 3;
    int m_cta = blockIdx.x * BM;

    int a_row = tid >> 2, a_c8 = tid & 3;

    float acc[2][4][4];
#pragma unroll
    for (int i = 0; i < 2; ++i)
#pragma unroll
        for (int j = 0; j < 4; ++j)
#pragma unroll
            for (int q = 0; q < 4; ++q) acc[i][j][q] = 0.f;

    const __half* Ag0 = g_Uh + (size_t)m_cta * KFH + kbase;

#define HLOAD(kt, buf)                                                         \
    {                                                                          \
        cpasync16(&As[buf][a_row * ASD + a_c8 * 8],                            \
                  Ag0 + (size_t)a_row * KFH + (kt) * BK + a_c8 * 8);           \
        _Pragma("unroll")                                                      \
        for (int i = 0; i < 2; ++i) {                                          \
            int f4 = tid + i * 256;                                            \
            int nn = f4 >> 2, c8 = f4 & 3;                                     \
            cpasync16(&Bs[buf][nn * BKD + c8 * 8],                             \
                      g_WhT + (size_t)nn * KFH + kbase + (kt) * BK + c8 * 8);  \
        }                                                                      \
        asm volatile("cp.async.commit_group;");                                \
    }

    constexpr int NT = KH4 / BK;   // 13
    HLOAD(0, 0);
    for (int kt = 0; kt < NT; ++kt) {
        asm volatile("cp.async.wait_group 0;");
        __syncthreads();
        if (kt + 1 < NT) HLOAD(kt + 1, (kt + 1) & 1);

        const __half* as = As[kt & 1];
        const __half* bs = Bs[kt & 1];
#pragma unroll
        for (int k16 = 0; k16 < 2; ++k16) {
            uint32_t af[2][4], bf[4][2];
#pragma unroll
            for (int mf = 0; mf < 2; ++mf) {
                int mrow = wm * 32 + mf * 16 + g;
                int kb = k16 * 16 + 2 * tq;
                af[mf][0] = *(const uint32_t*)&as[mrow * ASD + kb];
                af[mf][1] = *(const uint32_t*)&as[(mrow + 8) * ASD + kb];
                af[mf][2] = *(const uint32_t*)&as[mrow * ASD + kb + 8];
                af[mf][3] = *(const uint32_t*)&as[(mrow + 8) * ASD + kb + 8];
            }
#pragma unroll
            for (int nf = 0; nf < 4; ++nf) {
                int ncol = wn * 32 + nf * 8 + g;
                int kb = k16 * 16 + 2 * tq;
                bf[nf][0] = *(const uint32_t*)&bs[ncol * BKD + kb];
                bf[nf][1] = *(const uint32_t*)&bs[ncol * BKD + kb + 8];
            }
#pragma unroll
            for (int mf = 0; mf < 2; ++mf)
#pragma unroll
                for (int nf = 0; nf < 4; ++nf)
                    asm volatile(
                        "mma.sync.aligned.m16n8k16.row.col.f32.f16.f16.f32 "
                        "{%0,%1,%2,%3}, {%4,%5,%6,%7}, {%8,%9}, {%0,%1,%2,%3};"
                        : "+f"(acc[mf][nf][0]), "+f"(acc[mf][nf][1]),
                          "+f"(acc[mf][nf][2]), "+f"(acc[mf][nf][3])
                        : "r"(af[mf][0]), "r"(af[mf][1]),
                          "r"(af[mf][2]), "r"(af[mf][3]),
                          "r"(bf[nf][0]), "r"(bf[nf][1]));
        }
    }
#undef HLOAD

    float* __restrict__ Cp = g_CHp + (size_t)ks * NN * OH;
#pragma unroll
    for (int mf = 0; mf < 2; ++mf)
#pragma unroll
        for (int nf = 0; nf < 4; ++nf) {
            int row = m_cta + wm * 32 + mf * 16 + g;
            int col = wn * 32 + nf * 8 + 2 * tq;
            *(float2*)&Cp[(size_t)row * OH + col] =
                make_float2(acc[mf][nf][0], acc[mf][nf][1]);
            *(float2*)&Cp[(size_t)(row + 8) * OH + col] =
                make_float2(acc[mf][nf][2], acc[mf][nf][3]);
        }
}

// ---------------- gates: combine split-K partials + CX -----------------------
__global__ void k_gates(int t,
                        const float* __restrict__ bxr, const float* __restrict__ bhr,
                        const float* __restrict__ bxz, const float* __restrict__ bhz,
                        const float* __restrict__ bxn) {
    int idx = blockIdx.x * blockDim.x + threadIdx.x;
    if (idx >= NN * H) return;
    int n = idx >> 6, j = idx & 63;
    float hr = bhr[j], hz = bhz[j];
#pragma unroll
    for (int ks = 0; ks < NSK; ++ks) {
        const float* p = g_CHp + (size_t)ks * NN * OH + (size_t)n * OH;
        hr += p[j];
        hz += p[64 + j];
    }
    const float* cx = g_CX + ((size_t)t * NN + n) * OX;
    float r  = 1.f / (1.f + expf(-(cx[j]      + bxr[j] + hr)));
    float z  = 1.f / (1.f + expf(-(cx[64 + j] + bxz[j] + hz)));
    float nv = tanhf(cx[128 + j] + bxn[j] + r * hr);
    float hnew = (1.f - z) * nv + z * g_h[idx];
    g_h[idx] = hnew;
    g_hs[(size_t)t * NN * H + idx] = hnew;
}

// ---------------- outputs ----------------------------------------------------
__global__ void k_outT(float* __restrict__ out) {   // [t][n][h] -> [n][h][t]
    __shared__ float sm[1280];
    int tid = threadIdx.x;
    int ln = tid >> 6, j = tid & 63;
    int node = blockIdx.x * 2 + ln;
#pragma unroll
    for (int t = 0; t < TT; ++t)
        sm[ln * 640 + j * TT + t] = g_hs[(size_t)t * NN * H + (size_t)node * H + j];
    __syncthreads();
    const float* src = sm + ln * 640;
    float* dst = out + (size_t)node * (H * TT);
    for (int i = j; i < 640; i += 64) dst[i] = src[i];
}

__global__ void k_outlast(float* __restrict__ out) {
    int idx = blockIdx.x * blockDim.x + threadIdx.x;
    if (idx < NN * H) out[LOUT + idx] = g_h[idx];
}

// ---------------- launch -----------------------------------------------------
extern "C" void kernel_launch(void* const* d_in, const int* in_sizes, int n_in,
                              void* d_out, int out_size) {
    const float* x       = (const float*)d_in[0];
    const void*  ei      = d_in[1];                 // int64 or int32 (auto-detected)
    const float* attr    = (const float*)d_in[2];
    const float* W_xr    = (const float*)d_in[3];
    const float* root_xr = (const float*)d_in[4];
    const float* b_xr    = (const float*)d_in[5];
    const float* W_hr    = (const float*)d_in[6];
    const float* root_hr = (const float*)d_in[7];
    const float* b_hr    = (const float*)d_in[8];
    const float* W_xz    = (const float*)d_in[9];
    const float* root_xz = (const float*)d_in[10];
    const float* b_xz    = (const float*)d_in[11];
    const float* W_hz    = (const float*)d_in[12];
    const float* root_hz = (const float*)d_in[13];
    const float* b_hz    = (const float*)d_in[14];
    const float* W_xn    = (const float*)d_in[15];
    const float* root_xn = (const float*)d_in[16];
    const float* b_xn    = (const float*)d_in[17];
    float* out = (float*)d_out;

    // ---- prep chain (main stream) ----
    k_init<<<(NN * H + 255) / 256, 256>>>();
    k_detect<<<256, 256>>>((const long long*)ei);
    k_detect_fin<<<1, 1>>>();
    k_hist<<<NE / 256, 256>>>(ei);
    k_scan<<<1, 1024>>>();
    k_scatterpos<<<NE / 256, 256>>>(ei);
    k_sort<<<NN / 256, 256>>>();
    k_edgedata<<<NE / 256, 256>>>(ei, attr);
    k_xT<<<(NN * FIN) / 256, 256>>>(x);
    k_build_wxT<<<(OX * KFX + 255) / 256, 256>>>(W_xr, W_xz, W_xn, root_xr, root_xz, root_xn);
    k_build_whT<<<(OH * KFH + 255) / 256, 256>>>(W_hr, W_hz, root_hr, root_hz);

    // ---- fork x-side onto its own stream (overlaps with the recurrence) ----
    cudaEventRecord(s_fork, 0);
    cudaStreamWaitEvent(s_sx, s_fork, 0);
    k_scatter<FIN, true><<<dim3(NN / 8, TT), 256, 0, s_sx>>>(0);
    for (int t = 0; t < TT; ++t) {
        k_gemm_x<<<NN / 64, 256, 0, s_sx>>>(t);
        cudaEventRecord(s_evx[t], s_sx);
    }

    // ---- recurrence on main stream; gates(t) joins on CX(t) ----
    for (int t = 0; t < TT; ++t) {
        k_scatter<H, false><<<NN / 4, 256>>>(t);
        k_gemm_h_sk<<<dim3(NN / 64, NSK), 256>>>(t);
        cudaStreamWaitEvent(0, s_evx[t], 0);   // joins s_sx work up to x-GEMM(t)
        k_gates<<<(NN * H) / 256, 256>>>(t, b_xr, b_hr, b_xz, b_hz, b_xn);
    }

    // ---- outputs ----
    k_outT<<<NN / 2, 128>>>(out);
    k_outlast<<<(NN * H) / 256, 256>>>(out);
}

// round 17
// speedup vs baseline: 1.0948x; 1.0948x over previous
#include <cuda_runtime.h>
#include <cuda_fp16.h>
#include <stdint.h>
#include <math.h>

namespace {
constexpr int NB  = 8;
constexpr int NG  = 2048;
constexpr int FIN = 32;
constexpr int TT  = 10;
constexpr int H   = 64;
constexpr int NN  = NB * NG;          // 16384
constexpr int NE  = 262144;
constexpr int KFX = 26 * FIN;         // 832
constexpr int KFH = 26 * H;           // 1664
constexpr int NSK = 4;                // h-side split-K factor
constexpr int KH4 = KFH / NSK;        // 416 per split
constexpr int OX  = 192;
constexpr int OH  = 128;
constexpr long long LOUT = (long long)NN * H * TT;
}

// ---------------- scratch (device globals; allocation-free contract) --------
__device__ int    g_is64;
__device__ int    g_bad64;
__device__ int    g_cnt[NN];
__device__ int    g_cnt2[NN];
__device__ int    g_rowptr[NN + 1];
__device__ float  g_invdeg[NN];
__device__ int    g_eid[NE];
__device__ int    g_esrc[NE];
__device__ int    g_ew00[NE];
__device__ __align__(16) float4 g_eb[NE];
__device__ __align__(16) float  g_xT[(size_t)TT * NN * FIN];
__device__ __align__(16) __half g_Ux[(size_t)TT * NN * KFX];   // fp16 U (x side)
__device__ __align__(16) __half g_Uh[(size_t)NN * KFH];        // fp16 U (h side)
__device__ __align__(16) __half g_WxT[OX * KFX];               // [n][k] fp16
__device__ __align__(16) __half g_WhT[OH * KFH];               // [n][k] fp16
__device__ __align__(16) float  g_CX[(size_t)TT * NN * OX];
__device__ __align__(16) float  g_CHp[NSK * (size_t)NN * OH];  // split-K partials
__device__ __align__(16) float  g_h [(size_t)NN * H];
__device__ __align__(16) float  g_hs[(size_t)TT * NN * H];

// ---------------- helpers -----------------------------------------------------
__device__ __forceinline__ void cpasync16(void* smem, const void* g) {
    uint32_t s = (uint32_t)__cvta_generic_to_shared(smem);
    asm volatile("cp.async.ca.shared.global [%0], [%1], 16;\n" :: "r"(s), "l"(g));
}

// edge_index dtype helpers (int64 vs int32, decided at runtime by k_detect)
__device__ __forceinline__ int edge_src(const void* ei, int e) {
    return g_is64 ? (int)((const long long*)ei)[e] : ((const int*)ei)[e];
}
__device__ __forceinline__ int edge_dst(const void* ei, int e) {
    return g_is64 ? (int)((const long long*)ei)[NE + e] : ((const int*)ei)[NE + e];
}

// ---------------- init / dtype detection ------------------------------------
__global__ void k_init() {
    int idx = blockIdx.x * blockDim.x + threadIdx.x;
    if (idx < NN * H) g_h[idx] = 0.f;
    if (idx < NN) { g_cnt[idx] = 0; g_cnt2[idx] = 0; }
    if (idx == 0) { g_bad64 = 0; g_is64 = 1; }
}

__global__ void k_detect(const long long* __restrict__ ei64) {
    int i = blockIdx.x * blockDim.x + threadIdx.x;
    int bad = 0;
    for (; i < NE; i += gridDim.x * blockDim.x) {
        long long v = ei64[i];
        if (v < 0 || v >= NN) bad = 1;
    }
    if (__syncthreads_or(bad) && threadIdx.x == 0) atomicExch(&g_bad64, 1);
}
__global__ void k_detect_fin() { g_is64 = g_bad64 ? 0 : 1; }

// ---------------- graph preprocessing ----------------------------------------
__global__ void k_hist(const void* __restrict__ ei) {
    int e = blockIdx.x * blockDim.x + threadIdx.x;
    if (e < NE) atomicAdd(&g_cnt[edge_dst(ei, e)], 1);
}

__global__ void k_scan() {
    __shared__ int s[1024];
    __shared__ int carry;
    int tid = threadIdx.x;
    if (tid == 0) { carry = 0; g_rowptr[0] = 0; }
    __syncthreads();
    for (int c = 0; c < NN / 1024; ++c) {
        int i = c * 1024 + tid;
        int v = g_cnt[i];
        s[tid] = v;
        __syncthreads();
        for (int off = 1; off < 1024; off <<= 1) {
            int t = (tid >= off) ? s[tid - off] : 0;
            __syncthreads();
            s[tid] += t;
            __syncthreads();
        }
        g_rowptr[i + 1] = carry + s[tid];
        g_invdeg[i] = 1.0f / (float)max(v, 1);
        __syncthreads();
        if (tid == 0) carry += s[1023];
        __syncthreads();
    }
}

__global__ void k_scatterpos(const void* __restrict__ ei) {
    int e = blockIdx.x * blockDim.x + threadIdx.x;
    if (e < NE) {
        int dst = edge_dst(ei, e);
        g_eid[g_rowptr[dst] + atomicAdd(&g_cnt2[dst], 1)] = e;
    }
}

__global__ void k_sort() {   // deterministic per-bucket edge order
    int d = blockIdx.x * blockDim.x + threadIdx.x;
    if (d >= NN) return;
    int s0 = g_rowptr[d], e0 = g_rowptr[d + 1];
    for (int i = s0 + 1; i < e0; ++i) {
        int key = g_eid[i];
        int j = i - 1;
        while (j >= s0 && g_eid[j] > key) { g_eid[j + 1] = g_eid[j]; --j; }
        g_eid[j + 1] = key;
    }
}

__global__ void k_edgedata(const void* __restrict__ ei,
                           const float* __restrict__ attr) {
    int p = blockIdx.x * blockDim.x + threadIdx.x;
    if (p >= NE) return;
    int e = g_eid[p];
    float f0 = attr[2 * e]     * 4.0f;
    float f1 = attr[2 * e + 1] * 4.0f;
    int k0 = (int)floorf(f0); k0 = k0 < 0 ? 0 : (k0 > 3 ? 3 : k0);
    int k1 = (int)floorf(f1); k1 = k1 < 0 ? 0 : (k1 > 3 ? 3 : k1);
    float t0 = f0 - (float)k0, t1 = f1 - (float)k1;
    g_esrc[p] = edge_src(ei, e);
    g_ew00[p] = k0 + 5 * k1;
    g_eb[p] = make_float4((1.f - t0) * (1.f - t1), t0 * (1.f - t1),
                          (1.f - t0) * t1,          t0 * t1);
}

__global__ void k_xT(const float* __restrict__ x) {   // [n][f][t] -> [t][n][f]
    int idx = blockIdx.x * blockDim.x + threadIdx.x;
    if (idx >= NN * FIN) return;
    const float* src = x + (size_t)idx * TT;
#pragma unroll
    for (int t = 0; t < TT; ++t)
        g_xT[(size_t)t * NN * FIN + idx] = src[t];
}

// ---------------- weight concat: transposed [n][k], fp16 ---------------------
__global__ void k_build_wxT(const float* __restrict__ Wr, const float* __restrict__ Wz,
                            const float* __restrict__ Wn, const float* __restrict__ Rr,
                            const float* __restrict__ Rz, const float* __restrict__ Rn) {
    int idx = blockIdx.x * blockDim.x + threadIdx.x;
    if (idx >= OX * KFX) return;
    int n = idx / KFX, r = idx % KFX;
    int grp = n / 64, cc = n % 64;
    const float* W = (grp == 0) ? Wr : (grp == 1) ? Wz : Wn;
    const float* R = (grp == 0) ? Rr : (grp == 1) ? Rz : Rn;
    float val;
    if (r < 25 * FIN) { int k = r / FIN, f = r % FIN; val = W[((size_t)k * FIN + f) * H + cc]; }
    else              { int f = r - 25 * FIN;         val = R[(size_t)f * H + cc]; }
    g_WxT[idx] = __float2half_rn(val);
}

__global__ void k_build_whT(const float* __restrict__ Wr, const float* __restrict__ Wz,
                            const float* __restrict__ Rr, const float* __restrict__ Rz) {
    int idx = blockIdx.x * blockDim.x + threadIdx.x;
    if (idx >= OH * KFH) return;
    int n = idx / KFH, r = idx % KFH;
    int grp = n >> 6, cc = n & 63;
    const float* W = (grp == 0) ? Wr : Wz;
    const float* R = (grp == 0) ? Rr : Rz;
    float val;
    if (r < 25 * H) { int k = r / H, f = r % H; val = W[((size_t)k * H + f) * H + cc]; }
    else            { int f = r - 25 * H;       val = R[(size_t)f * H + cc]; }
    g_WhT[idx] = __float2half_rn(val);
}

// ---------------- scatter-aggregate (emits fp16 U) ---------------------------
template<int FV, bool XM>
__global__ void k_scatter(int tparam) {
    constexpr int NPC = 256 / FV;
    __shared__ float acc[NPC * 25 * FV];
    int t     = XM ? blockIdx.y : tparam;
    int tid   = threadIdx.x;
    int local = tid / FV;
    int f     = tid % FV;
    int node  = blockIdx.x * NPC + local;
    float* a = acc + local * (25 * FV) + f;
#pragma unroll
    for (int k = 0; k < 25; ++k) a[k * FV] = 0.f;

    const float* __restrict__ v = XM ? (g_xT + (size_t)t * NN * FIN) : g_h;
    int s = g_rowptr[node], e = g_rowptr[node + 1];
    for (int p = s; p < e; ++p) {
        float  vf = v[(size_t)g_esrc[p] * FV + f];
        float4 b  = g_eb[p];
        float* q  = a + g_ew00[p] * FV;
        q[0]      += b.x * vf;
        q[FV]     += b.y * vf;
        q[5 * FV] += b.z * vf;
        q[6 * FV] += b.w * vf;
    }
    float id = g_invdeg[node];
    __half* __restrict__ U = XM ? (g_Ux + (size_t)t * NN * KFX) : g_Uh;
    size_t ro = (size_t)node * (26 * FV);
#pragma unroll
    for (int k = 0; k < 25; ++k) U[ro + k * FV + f] = __float2half_rn(a[k * FV] * id);
    U[ro + 25 * FV + f] = __float2half_rn(v[(size_t)node * FV + f]);
}

// ---------------- x-side FP16 GEMM: BM=64, BN=192 (full), BK=32, occ 3 -------
// CX[t][N][192] = Ux[t][N][832] x WxT[192][832]^T  (batched over t via z)
__global__ __launch_bounds__(256, 3)
void k_gemm_x() {
    constexpr int BM = 64, BK = 32;
    constexpr int ASD = BK + 8;    // 40 halves
    constexpr int BKD = BK + 8;    // 40 halves, B stored [n][k]
    __shared__ __half As[2][BM * ASD];
    __shared__ __half Bs[2][OX * BKD];

    int t = blockIdx.z;
    const __half* __restrict__ A = g_Ux + (size_t)t * NN * KFX;
    float* __restrict__ C        = g_CX + (size_t)t * NN * OX;

    int tid  = threadIdx.x;
    int lane = tid & 31, w = tid >> 5;
    int wm = w >> 2, wn = w & 3;
    int g  = lane >> 2, tq = lane & 3;
    int m_cta = blockIdx.x * BM;

    int a_row = tid >> 2, a_c8 = tid & 3;

    float acc[2][6][4];
#pragma unroll
    for (int i = 0; i < 2; ++i)
#pragma unroll
        for (int j = 0; j < 6; ++j)
#pragma unroll
            for (int q = 0; q < 4; ++q) acc[i][j][q] = 0.f;

    const __half* Ag0 = A + (size_t)m_cta * KFX;

#define XLOAD(kt, buf)                                                         \
    {                                                                          \
        cpasync16(&As[buf][a_row * ASD + a_c8 * 8],                            \
                  Ag0 + (size_t)a_row * KFX + (kt) * BK + a_c8 * 8);           \
        _Pragma("unroll")                                                      \
        for (int i = 0; i < 3; ++i) {                                          \
            int f4 = tid + i * 256;                                            \
            int nn = f4 >> 2, c8 = f4 & 3;                                     \
            cpasync16(&Bs[buf][nn * BKD + c8 * 8],                             \
                      g_WxT + (size_t)nn * KFX + (kt) * BK + c8 * 8);          \
        }                                                                      \
        asm volatile("cp.async.commit_group;");                                \
    }

    constexpr int NT = KFX / BK;   // 26
    XLOAD(0, 0);
    for (int kt = 0; kt < NT; ++kt) {
        asm volatile("cp.async.wait_group 0;");
        __syncthreads();
        if (kt + 1 < NT) XLOAD(kt + 1, (kt + 1) & 1);

        const __half* as = As[kt & 1];
        const __half* bs = Bs[kt & 1];
#pragma unroll
        for (int k16 = 0; k16 < 2; ++k16) {
            uint32_t af[2][4], bf[6][2];
#pragma unroll
            for (int mf = 0; mf < 2; ++mf) {
                int mrow = wm * 32 + mf * 16 + g;
                int kb = k16 * 16 + 2 * tq;
                af[mf][0] = *(const uint32_t*)&as[mrow * ASD + kb];
                af[mf][1] = *(const uint32_t*)&as[(mrow + 8) * ASD + kb];
                af[mf][2] = *(const uint32_t*)&as[mrow * ASD + kb + 8];
                af[mf][3] = *(const uint32_t*)&as[(mrow + 8) * ASD + kb + 8];
            }
#pragma unroll
            for (int nf = 0; nf < 6; ++nf) {
                int ncol = wn * 48 + nf * 8 + g;
                int kb = k16 * 16 + 2 * tq;
                bf[nf][0] = *(const uint32_t*)&bs[ncol * BKD + kb];
                bf[nf][1] = *(const uint32_t*)&bs[ncol * BKD + kb + 8];
            }
#pragma unroll
            for (int mf = 0; mf < 2; ++mf)
#pragma unroll
                for (int nf = 0; nf < 6; ++nf)
                    asm volatile(
                        "mma.sync.aligned.m16n8k16.row.col.f32.f16.f16.f32 "
                        "{%0,%1,%2,%3}, {%4,%5,%6,%7}, {%8,%9}, {%0,%1,%2,%3};"
                        : "+f"(acc[mf][nf][0]), "+f"(acc[mf][nf][1]),
                          "+f"(acc[mf][nf][2]), "+f"(acc[mf][nf][3])
                        : "r"(af[mf][0]), "r"(af[mf][1]),
                          "r"(af[mf][2]), "r"(af[mf][3]),
                          "r"(bf[nf][0]), "r"(bf[nf][1]));
        }
    }
#undef XLOAD

#pragma unroll
    for (int mf = 0; mf < 2; ++mf)
#pragma unroll
        for (int nf = 0; nf < 6; ++nf) {
            int row = m_cta + wm * 32 + mf * 16 + g;
            int col = wn * 48 + nf * 8 + 2 * tq;
            *(float2*)&C[(size_t)row * OX + col] =
                make_float2(acc[mf][nf][0], acc[mf][nf][1]);
            *(float2*)&C[(size_t)(row + 8) * OX + col] =
                make_float2(acc[mf][nf][2], acc[mf][nf][3]);
        }
}

// ---------------- h-side FP16 GEMM, split-K=4, occ 4 -------------------------
// CHp[ks][N][128] = Uh[N][ks*416 .. +416] x WhT[128][same]^T
__global__ __launch_bounds__(256, 4)
void k_gemm_h_sk(int t) {
    constexpr int BM = 64, BK = 32;
    constexpr int ASD = BK + 8;    // 40 halves
    constexpr int BKD = BK + 8;    // 40 halves
    __shared__ __half As[2][BM * ASD];
    __shared__ __half Bs[2][OH * BKD];

    int ks = blockIdx.y;
    int kbase = ks * KH4;

    int tid  = threadIdx.x;
    int lane = tid & 31, w = tid >> 5;
    int wm = w >> 2, wn = w & 3;
    int g  = lane >> 2, tq = lane & 3;
    int m_cta = blockIdx.x * BM;

    int a_row = tid >> 2, a_c8 = tid & 3;

    float acc[2][4][4];
#pragma unroll
    for (int i = 0; i < 2; ++i)
#pragma unroll
        for (int j = 0; j < 4; ++j)
#pragma unroll
            for (int q = 0; q < 4; ++q) acc[i][j][q] = 0.f;

    const __half* Ag0 = g_Uh + (size_t)m_cta * KFH + kbase;

#define HLOAD(kt, buf)                                                         \
    {                                                                          \
        cpasync16(&As[buf][a_row * ASD + a_c8 * 8],                            \
                  Ag0 + (size_t)a_row * KFH + (kt) * BK + a_c8 * 8);           \
        _Pragma("unroll")                                                      \
        for (int i = 0; i < 2; ++i) {                                          \
            int f4 = tid + i * 256;                                            \
            int nn = f4 >> 2, c8 = f4 & 3;                                     \
            cpasync16(&Bs[buf][nn * BKD + c8 * 8],                             \
                      g_WhT + (size_t)nn * KFH + kbase + (kt) * BK + c8 * 8);  \
        }                                                                      \
        asm volatile("cp.async.commit_group;");                                \
    }

    constexpr int NT = KH4 / BK;   // 13
    HLOAD(0, 0);
    for (int kt = 0; kt < NT; ++kt) {
        asm volatile("cp.async.wait_group 0;");
        __syncthreads();
        if (kt + 1 < NT) HLOAD(kt + 1, (kt + 1) & 1);

        const __half* as = As[kt & 1];
        const __half* bs = Bs[kt & 1];
#pragma unroll
        for (int k16 = 0; k16 < 2; ++k16) {
            uint32_t af[2][4], bf[4][2];
#pragma unroll
            for (int mf = 0; mf < 2; ++mf) {
                int mrow = wm * 32 + mf * 16 + g;
                int kb = k16 * 16 + 2 * tq;
                af[mf][0] = *(const uint32_t*)&as[mrow * ASD + kb];
                af[mf][1] = *(const uint32_t*)&as[(mrow + 8) * ASD + kb];
                af[mf][2] = *(const uint32_t*)&as[mrow * ASD + kb + 8];
                af[mf][3] = *(const uint32_t*)&as[(mrow + 8) * ASD + kb + 8];
            }
#pragma unroll
            for (int nf = 0; nf < 4; ++nf) {
                int ncol = wn * 32 + nf * 8 + g;
                int kb = k16 * 16 + 2 * tq;
                bf[nf][0] = *(const uint32_t*)&bs[ncol * BKD + kb];
                bf[nf][1] = *(const uint32_t*)&bs[ncol * BKD + kb + 8];
            }
#pragma unroll
            for (int mf = 0; mf < 2; ++mf)
#pragma unroll
                for (int nf = 0; nf < 4; ++nf)
                    asm volatile(
                        "mma.sync.aligned.m16n8k16.row.col.f32.f16.f16.f32 "
                        "{%0,%1,%2,%3}, {%4,%5,%6,%7}, {%8,%9}, {%0,%1,%2,%3};"
                        : "+f"(acc[mf][nf][0]), "+f"(acc[mf][nf][1]),
                          "+f"(acc[mf][nf][2]), "+f"(acc[mf][nf][3])
                        : "r"(af[mf][0]), "r"(af[mf][1]),
                          "r"(af[mf][2]), "r"(af[mf][3]),
                          "r"(bf[nf][0]), "r"(bf[nf][1]));
        }
    }
#undef HLOAD

    float* __restrict__ Cp = g_CHp + (size_t)ks * NN * OH;
#pragma unroll
    for (int mf = 0; mf < 2; ++mf)
#pragma unroll
        for (int nf = 0; nf < 4; ++nf) {
            int row = m_cta + wm * 32 + mf * 16 + g;
            int col = wn * 32 + nf * 8 + 2 * tq;
            *(float2*)&Cp[(size_t)row * OH + col] =
                make_float2(acc[mf][nf][0], acc[mf][nf][1]);
            *(float2*)&Cp[(size_t)(row + 8) * OH + col] =
                make_float2(acc[mf][nf][2], acc[mf][nf][3]);
        }
}

// ---------------- gates: combine split-K partials + CX -----------------------
__global__ void k_gates(int t,
                        const float* __restrict__ bxr, const float* __restrict__ bhr,
                        const float* __restrict__ bxz, const float* __restrict__ bhz,
                        const float* __restrict__ bxn) {
    int idx = blockIdx.x * blockDim.x + threadIdx.x;
    if (idx >= NN * H) return;
    int n = idx >> 6, j = idx & 63;
    float hr = bhr[j], hz = bhz[j];
#pragma unroll
    for (int ks = 0; ks < NSK; ++ks) {
        const float* p = g_CHp + (size_t)ks * NN * OH + (size_t)n * OH;
        hr += p[j];
        hz += p[64 + j];
    }
    const float* cx = g_CX + ((size_t)t * NN + n) * OX;
    float r  = 1.f / (1.f + expf(-(cx[j]      + bxr[j] + hr)));
    float z  = 1.f / (1.f + expf(-(cx[64 + j] + bxz[j] + hz)));
    float nv = tanhf(cx[128 + j] + bxn[j] + r * hr);
    float hnew = (1.f - z) * nv + z * g_h[idx];
    g_h[idx] = hnew;
    g_hs[(size_t)t * NN * H + idx] = hnew;
}

// ---------------- outputs (merged: layer_output + last_state) ----------------
__global__ void k_out(float* __restrict__ out) {
    __shared__ float sm[1280];
    int tid = threadIdx.x;
    int ln = tid >> 6, j = tid & 63;
    int node = blockIdx.x * 2 + ln;
#pragma unroll
    for (int t = 0; t < TT; ++t)
        sm[ln * 640 + j * TT + t] = g_hs[(size_t)t * NN * H + (size_t)node * H + j];
    __syncthreads();
    const float* src = sm + ln * 640;
    float* dst = out + (size_t)node * (H * TT);
    for (int i = j; i < 640; i += 64) dst[i] = src[i];
    // last_state appended after layer_output
    out[LOUT + (size_t)node * H + j] = g_h[(size_t)node * H + j];
}

// ---------------- launch -----------------------------------------------------
extern "C" void kernel_launch(void* const* d_in, const int* in_sizes, int n_in,
                              void* d_out, int out_size) {
    const float* x       = (const float*)d_in[0];
    const void*  ei      = d_in[1];                 // int64 or int32 (auto-detected)
    const float* attr    = (const float*)d_in[2];
    const float* W_xr    = (const float*)d_in[3];
    const float* root_xr = (const float*)d_in[4];
    const float* b_xr    = (const float*)d_in[5];
    const float* W_hr    = (const float*)d_in[6];
    const float* root_hr = (const float*)d_in[7];
    const float* b_hr    = (const float*)d_in[8];
    const float* W_xz    = (const float*)d_in[9];
    const float* root_xz = (const float*)d_in[10];
    const float* b_xz    = (const float*)d_in[11];
    const float* W_hz    = (const float*)d_in[12];
    const float* root_hz = (const float*)d_in[13];
    const float* b_hz    = (const float*)d_in[14];
    const float* W_xn    = (const float*)d_in[15];
    const float* root_xn = (const float*)d_in[16];
    const float* b_xn    = (const float*)d_in[17];
    float* out = (float*)d_out;

    // prep chain
    k_init<<<(NN * H + 255) / 256, 256>>>();
    k_detect<<<256, 256>>>((const long long*)ei);
    k_detect_fin<<<1, 1>>>();
    k_hist<<<NE / 256, 256>>>(ei);
    k_scan<<<1, 1024>>>();
    k_scatterpos<<<NE / 256, 256>>>(ei);
    k_sort<<<NN / 256, 256>>>();
    k_edgedata<<<NE / 256, 256>>>(ei, attr);
    k_xT<<<(NN * FIN) / 256, 256>>>(x);
    k_build_wxT<<<(OX * KFX + 255) / 256, 256>>>(W_xr, W_xz, W_xn, root_xr, root_xz, root_xn);
    k_build_whT<<<(OH * KFH + 255) / 256, 256>>>(W_hr, W_hz, root_hr, root_hz);

    // x-side convs: all timesteps batched (single launches; best wave packing)
    k_scatter<FIN, true><<<dim3(NN / 8, TT), 256>>>(0);
    k_gemm_x<<<dim3(NN / 64, 1, TT), 256>>>();

    // recurrence: scatter h, split-K GEMM, gates
    for (int t = 0; t < TT; ++t) {
        k_scatter<H, false><<<NN / 4, 256>>>(t);
        k_gemm_h_sk<<<dim3(NN / 64, NSK), 256>>>(t);
        k_gates<<<(NN * H) / 256, 256>>>(t, b_xr, b_hr, b_xz, b_hz, b_xn);
    }

    // outputs (single merged kernel)
    k_out<<<NN / 2, 128>>>(out);
}